// round 12
// baseline (speedup 1.0000x reference)
#include <cuda_runtime.h>

#define V_SIZE 128000
#define V4 32000               // V_SIZE/4 quads
#define NWIN 125               // windows of 256 quads (V4/256)
#define NBY 64                 // sibling blocks per window (one per batch row)
#define R_MAX 512
#define PEN_LAMBDA 0.5f

// Scratch (__device__ globals; zero-initialized at load).
// Invariant: every execution leaves scratch at zero (consume-and-reset).
__device__ float g_pen[V_SIZE];
__device__ float g_pen_head[NWIN * 4];   // replica of each window's first quad
__device__ float g_firing[R_MAX];
__device__ int   g_tick[NWIN];

// ---------------------------------------------------------------------------
// k_scatter: pen[token] += sigmoid(gate_logit[rule]) * lambda
// 245 blocks x 512 threads, 2 quads (8 pairs)/thread. Gates (lambda folded)
// + firing flags in smem; firing flushed once per CTA. Tokens in a window's
// first quad also add into g_pen_head (replica consumed by k_main).
// ---------------------------------------------------------------------------
__device__ __forceinline__ void scatter_one(int t, float v) {
    atomicAdd(&g_pen[t], v);
    if ((t & 1023) < 4)
        atomicAdd(&g_pen_head[((t >> 10) << 2) | (t & 3)], v);
}

__global__ void __launch_bounds__(512) k_scatter(
    const float* __restrict__ gate_logits,
    const int* __restrict__ rule_ids,
    const int* __restrict__ token_ids,
    int n_quads)   // E/4
{
    __shared__ float s_gates[R_MAX];
    __shared__ int   s_fire[R_MAX];
    int tid = threadIdx.x;
    s_gates[tid] = PEN_LAMBDA / (1.0f + __expf(-gate_logits[tid]));
    s_fire[tid] = 0;
    __syncthreads();

    #pragma unroll
    for (int p = 0; p < 2; p++) {
        int q = blockIdx.x * 1024 + p * 512 + tid;
        if (q < n_quads) {
            int4 r = reinterpret_cast<const int4*>(rule_ids)[q];
            int4 t = reinterpret_cast<const int4*>(token_ids)[q];
            scatter_one(t.x, s_gates[r.x]);
            scatter_one(t.y, s_gates[r.y]);
            scatter_one(t.z, s_gates[r.z]);
            scatter_one(t.w, s_gates[r.w]);
            s_fire[r.x] = 1;
            s_fire[r.y] = 1;
            s_fire[r.z] = 1;
            s_fire[r.w] = 1;
        }
    }
    __syncthreads();
    if (s_fire[tid]) g_firing[tid] = 1.0f;   // idempotent across CTAs
}

// ---------------------------------------------------------------------------
// k_main: fused broadcast + penalties + loss + deferred ticketed reset.
// Grid (125, 64), 256 threads: block (bx, by) = window bx, batch row by.
// Per thread: stage one pen quad to smem -> 1 logits LDG.128 ->
// 2 STG.128 (modified + shifted penalties). Maximum warp parallelism
// (8000 CTAs), minimal per-thread latency chain.
// Ticket: atomicAdd at entry (latency hidden by the body); the 64th-arriving
// sibling zeroes the window + next head replica + ticket after its stores.
// ---------------------------------------------------------------------------
__global__ void __launch_bounds__(256) k_main(
    const float* __restrict__ logits,
    const float* __restrict__ gate_logits,
    float* __restrict__ modified,
    float* __restrict__ penalties,   // = out + BV + 1 (4B-aligned)
    float* __restrict__ out_loss,
    int pen_quads)                   // (BV-3)/4
{
    __shared__ float s_pen[1028];
    __shared__ int   s_last;
    int tid = threadIdx.x;
    int bx  = blockIdx.x;
    int by  = blockIdx.y;
    int m0  = bx * 256;
    int wn  = (bx + 1 == NWIN) ? 0 : bx + 1;

    // stage own window + tail replica (from next window's head copy)
    reinterpret_cast<float4*>(s_pen)[tid] =
        reinterpret_cast<const float4*>(g_pen)[m0 + tid];
    if (tid < 4) s_pen[1024 + tid] = g_pen_head[wn * 4 + tid];

    // ticket "I will have staged by the next barrier" — consumed after stores
    if (tid == 0)
        s_last = (atomicAdd(&g_tick[bx], 1) == NBY - 1);
    __syncthreads();

    // coverage loss: one warp of block (0,0); reads + resets g_firing
    if (bx == 0 && by == 0 && (tid >> 5) == 1) {
        int lt = tid & 31;
        float f = 0.0f, gf = 0.0f;
        #pragma unroll
        for (int k = 0; k < 16; k++) {
            int i = lt + 32 * k;
            float fi = g_firing[i];
            float gi = 1.0f / (1.0f + __expf(-gate_logits[i]));
            f += fi;
            gf += gi * fi;
            g_firing[i] = 0.0f;
        }
        #pragma unroll
        for (int off = 16; off > 0; off >>= 1) {
            gf += __shfl_down_sync(0xFFFFFFFF, gf, off);
            f  += __shfl_down_sync(0xFFFFFFFF, f,  off);
        }
        if (lt == 0) {
            out_loss[0] = -gf / fmaxf(f, 1.0f);
            penalties[0] = s_pen[0];
            penalties[1] = s_pen[1];
            penalties[2] = s_pen[2];
        }
    }
    if (bx == NWIN - 1 && by == NBY - 1 && tid == 255) {
        // last penalties element: pen[V-1] == s_pen[1023] of last window
        penalties[(int64_t)64 * V_SIZE - 1] = s_pen[1023];
    }

    float4 p  = reinterpret_cast<const float4*>(s_pen)[tid];
    float4 pn = reinterpret_cast<const float4*>(s_pen)[tid + 1];
    float4 ps = make_float4(p.w, pn.x, pn.y, pn.z);

    int i = by * V4 + m0 + tid;       // global quad index for this thread
    float4 l = __ldg(reinterpret_cast<const float4*>(logits) + i);
    float4 o;
    o.x = l.x - p.x; o.y = l.y - p.y; o.z = l.z - p.z; o.w = l.w - p.w;
    __stcs(reinterpret_cast<float4*>(modified) + i, o);
    if (i < pen_quads)
        __stcs(reinterpret_cast<float4*>(penalties + 3) + i, ps);

    // deferred reset by the last-arriving sibling (all 64 readers staged)
    __syncthreads();
    if (s_last) {
        reinterpret_cast<float4*>(g_pen)[m0 + tid] =
            make_float4(0.f, 0.f, 0.f, 0.f);
        if (tid < 4) g_pen_head[wn * 4 + tid] = 0.0f;
        if (tid == 0) g_tick[bx] = 0;
    }
}

extern "C" void kernel_launch(void* const* d_in, const int* in_sizes, int n_in,
                              void* d_out, int out_size) {
    const float* logits      = (const float*)d_in[0];
    const float* gate_logits = (const float*)d_in[1];
    const int*   rule_ids    = (const int*)d_in[2];
    const int*   token_ids   = (const int*)d_in[3];

    int BV = in_sizes[0];       // 8,192,000
    int E  = in_sizes[2];       // 1,000,000

    float* out       = (float*)d_out;
    float* modified  = out;                 // [BV]
    float* out_loss  = out + BV;            // [1]
    float* penalties = out + BV + 1;        // [BV], 4B-aligned

    // 1) scatter (scratch arrives zeroed: initial state or previous k_main)
    {
        int n_quads = E / 4;                        // 250,000
        int blocks = (n_quads + 1023) / 1024;       // 245
        k_scatter<<<blocks, 512>>>(gate_logits, rule_ids, token_ids, n_quads);
    }
    // 2) fused broadcast + penalties + loss + deferred reset
    {
        int pen_quads = (BV - 3) / 4;               // 2,047,999
        dim3 grid(NWIN, NBY);                       // (125, 64)
        k_main<<<grid, 256>>>(logits, gate_logits, modified, penalties,
                              out_loss, pen_quads);
    }
}